// round 14
// baseline (speedup 1.0000x reference)
#include <cuda_runtime.h>
#include <math.h>

#define NB 4096
#define NK 1024
#define ND 128
#define NQ 2048
#define EPSV 1e-6f
#define SCALE 4294967296.0    // 2^32 fixed-point for deterministic final accum
#define FPS 65536.0f          // 2^16 fixed-point for warp-sum redux
#define CNT_SHIFT 50          // row-counter bits in the global accumulator

typedef unsigned long long u64;
typedef unsigned int u32;

// Scratch (device globals — no allocation allowed in kernel_launch)
__device__ u64    g_skey[ND * NK];     // sorted packed keys, layout [d][i]
__device__ u32    g_lutpair[ND * NQ];  // per-bucket start|end<<16 (fallback only)
__device__ uint4  g_rec[ND * NQ];      // 16B: kl_enc,k0_enc,k1_enc, idx+cnt pack
__device__ uint4  g_ext[ND];           // per-dim extremes: vmin,vmax,imin,imax
__device__ u64    g_accum;             // fixed-point sum + row counter (bits 50+)

// float -> order-preserving u32 (ascending)
__device__ __forceinline__ u32 enc_f32(float v) {
    u32 b = __float_as_uint(v);
    return (b & 0x80000000u) ? ~b : (b | 0x80000000u);
}
__device__ __forceinline__ float dec_f32(u32 u) {
    u32 b = (u & 0x80000000u) ? (u ^ 0x80000000u) : ~u;
    return __uint_as_float(b);
}

// Exactly monotone bucket map: fp add, mul by +const, float->int trunc are all
// monotone nondecreasing, so v1 <= v2 => bucket(v1) <= bucket(v2), and
// b1 < b2 => v1 < v2 (strict). Equal values map to equal buckets.
__device__ __forceinline__ int bucket_of(float v) {
    float f = (v + 6.0f) * ((float)NQ / 12.0f);
    f = fminf(fmaxf(f, 0.0f), (float)(NQ - 1));
    return (int)f;
}

// ---------------------------------------------------------------------------
// Kernel 1: per-column COUNTING sort of packed (value,index) u64 keys.
// 1024 threads, one element per thread. Fused lutpair + record emission.
// ---------------------------------------------------------------------------
__global__ void __launch_bounds__(1024) sort_columns_kernel(const float* __restrict__ cent) {
    __shared__ __align__(16) int s_hist[NQ];       // 8 KB
    __shared__ __align__(16) int s_pref[NQ + 4];   // 8 KB (exclusive prefix)
    __shared__ u64 s_tmp[NK];                      // 8 KB (arrival-order scatter)
    __shared__ u64 s_keys[NK];                     // 8 KB (final sorted)
    __shared__ int s_wsum[32];

    const int d = blockIdx.x;
    const int i = threadIdx.x;
    const int lane = i & 31, w = i >> 5;

    if (d == 0 && i == 0) g_accum = 0ULL;   // per-launch accumulator reset

    const float v = cent[i * ND + d];
    const u64 key = ((u64)enc_f32(v) << 32) | (u32)i;
    const int bkt = bucket_of(v);

    ((int2*)s_hist)[i] = make_int2(0, 0);   // NQ ints = 1024 int2
    __syncthreads();
    const int r = atomicAdd(&s_hist[bkt], 1);
    __syncthreads();

    // prefix sum over 2048 bins (2 per thread)
    const int2 c = ((const int2*)s_hist)[i];
    const int s = c.x + c.y;
    int incl = s;
#pragma unroll
    for (int off = 1; off < 32; off <<= 1) {
        int t = __shfl_up_sync(0xffffffffu, incl, off);
        if (lane >= off) incl += t;
    }
    if (lane == 31) s_wsum[w] = incl;
    __syncthreads();
    if (w == 0) {
        int ws = s_wsum[lane];
#pragma unroll
        for (int off = 1; off < 32; off <<= 1) {
            int t = __shfl_up_sync(0xffffffffu, ws, off);
            if (lane >= off) ws += t;
        }
        s_wsum[lane] = ws;
    }
    __syncthreads();
    {
        int p0 = (w > 0 ? s_wsum[w - 1] : 0) + (incl - s);
        ((int2*)s_pref)[i] = make_int2(p0, p0 + c.x);
    }
    if (i == 0) s_pref[NQ] = NK;
    __syncthreads();

    // scatter in arrival order
    const int st = s_pref[bkt];
    s_tmp[st + r] = key;
    __syncthreads();

    // parallel rank placement on unique full keys (deterministic)
    {
        const int cnt = s_hist[bkt];
        int rank = 0;
        for (int j = 0; j < cnt; j++) rank += (s_tmp[st + j] < key);
        s_keys[st + rank] = key;
    }
    __syncthreads();

    g_skey[d * NK + i] = s_keys[i];   // coalesced

    // lutpair + record: 2 buckets per thread, from smem-resident data
#pragma unroll
    for (int t = 0; t < 2; t++) {
        const int q = i + t * 1024;
        const int qs = s_pref[q], qe = s_pref[q + 1];
        g_lutpair[d * NQ + q] = (u32)qs | ((u32)qe << 16);
        const u64 kl = s_keys[max(qs - 1, 0)];
        const u64 k0 = s_keys[min(qs, NK - 1)];
        const u64 k1 = s_keys[min(qs + 1, NK - 1)];
        const u32 cc = (u32)min(qe - qs, 3);
        g_rec[d * NQ + q] = make_uint4(
            (u32)(kl >> 32), (u32)(k0 >> 32), (u32)(k1 >> 32),
            ((u32)kl & 1023u) | (((u32)k0 & 1023u) << 10) |
            (((u32)k1 & 1023u) << 20) | (cc << 30));
    }

    if (i == 0) {
        // min: first sorted key already has smallest index among min-ties.
        // max: first occurrence (smallest idx) = start of the max-value run.
        u32 umax = (u32)(s_keys[NK - 1] >> 32);
        int j = NK - 1;
        while (j > 0 && (u32)(s_keys[j - 1] >> 32) == umax) j--;
        g_ext[d] = make_uint4(
            __float_as_uint(dec_f32((u32)(s_keys[0] >> 32))),
            __float_as_uint(dec_f32(umax)),
            (u32)(s_keys[0] & 1023u),
            (u32)(s_keys[j] & 1023u));
    }
}

// ---------------------------------------------------------------------------
// Nearest-centroid resolve: one 16B record load resolves most queries
// (cnt<=1 or target<=k1); fallback loads lutpair + scans sorted keys.
// ---------------------------------------------------------------------------
__device__ __forceinline__ int resolve_near(const float xv, const int d) {
    const u32 te = enc_f32(xv);
    const int q = bucket_of(xv);
    const uint4 r = __ldg(&g_rec[d * NQ + q]);
    const u32 cc = r.w >> 30;

    u32 el, er, il, ir;
    if (cc == 0u || te <= r.y) {              // lower_bound = start
        el = r.x; il = r.w & 1023u;
        er = r.y; ir = (r.w >> 10) & 1023u;
    } else if (cc == 1u || te <= r.z) {       // lower_bound = start+1
        el = r.y; il = (r.w >> 10) & 1023u;
        er = r.z; ir = (r.w >> 20) & 1023u;
    } else {                                  // cnt>=2 and target beyond k1
        const u32 pr = __ldg(&g_lutpair[d * NQ + q]);
        const int st = (int)(pr & 0xffffu), en = (int)(pr >> 16);
        const int base = d * NK;
        const u64 target = ((u64)te) << 32;
        u64 prev = ((u64)r.z << 32) | ((r.w >> 20) & 1023u);
        u64 right = prev;
        bool found = false;
        for (int j = st + 2; j < en; j++) {
            u64 cur = __ldg(&g_skey[base + j]);
            if (cur >= target) { right = cur; found = true; break; }
            prev = cur;
        }
        if (!found) right = (en < NK) ? __ldg(&g_skey[base + en]) : prev;
        el = (u32)(prev >> 32);  il = (u32)prev & 1023u;
        er = (u32)(right >> 32); ir = (u32)right & 1023u;
    }

    const float vl = dec_f32(el), vr = dec_f32(er);
    float sl = xv - vl; sl *= sl;     // compare squares, like reference
    float sr = xv - vr; sr *= sr;
    return (sl < sr) ? (int)il : (sr < sl) ? (int)ir : min((int)il, (int)ir);
}

// ---------------------------------------------------------------------------
// Kernel 2: FOUR WARPS PER ROW, one dim per thread, one row per 128-thread
// block -> 16384 warps chip-wide (2x r13) for latency hiding. Per-thread
// critical path halves: ONE resolve, ONE ext load, TWO atomics. Warp
// reductions are single redux.sync; 4-warp combine via smem + __syncthreads.
// __launch_bounds__(128,16): 16 blocks/SM = full 64-warp residency.
// ---------------------------------------------------------------------------
__global__ void __launch_bounds__(ND, 16) row_kernel(const float* __restrict__ x,
                                                     const float* __restrict__ cent,
                                                     float* __restrict__ out) {
    __shared__ u32 hist[NK];          // 4 KB: near | far<<16
    __shared__ u32 s_keys[4][2];      // per-warp partial mode keys (N, F)
    __shared__ u32 s_part[4][3];      // per-warp fixed-point distance sums

    const int d = threadIdx.x;        // dim handled by this thread
    const int warp = d >> 5, lane = d & 31;
    const int row = blockIdx.x;

    // zero hist: 256 uint4 / 128 threads = 2 each
    {
        uint4 z = make_uint4(0, 0, 0, 0);
        ((uint4*)hist)[d] = z;
        ((uint4*)hist)[d + 128] = z;
    }

    const float xv = __ldg(&x[row * ND + d]);   // coalesced LDG.32

    const int n0 = resolve_near(xv, d);

    // farthest: one of the column extremes (one LDG.128)
    int f0;
    {
        const uint4 e = __ldg(&g_ext[d]);
        float sm = xv - __uint_as_float(e.x); sm *= sm;
        float sM = xv - __uint_as_float(e.y); sM *= sM;
        f0 = (sm > sM) ? (int)e.z : (sM > sm) ? (int)e.w : min((int)e.z, (int)e.w);
    }

    __syncthreads();   // zeroing visible

    // histogram (u16 lanes: near low, far high; counts <= 128, no carry)
    u32 keyN, keyF;
    {
        u32 cn = ( atomicAdd(&hist[n0], 1u)       & 0xffffu) + 1u;
        u32 cf = ((atomicAdd(&hist[f0], 0x10000u) >> 16)    ) + 1u;
        keyN = (cn << 10) | (1023u - (u32)n0);
        keyF = (cf << 10) | (1023u - (u32)f0);
    }
    // single-instruction warp reductions; running-max mode trick composes:
    // the globally-last increment of a bin carries the final count.
    keyN = __reduce_max_sync(0xffffffffu, keyN);
    keyF = __reduce_max_sync(0xffffffffu, keyF);
    if (lane == 0) { s_keys[warp][0] = keyN; s_keys[warp][1] = keyF; }
    __syncthreads();

    // combine the 4 warps' partial keys -> row mode
    const u32 kN = max(max(s_keys[0][0], s_keys[1][0]), max(s_keys[2][0], s_keys[3][0]));
    const u32 kF = max(max(s_keys[0][1], s_keys[1][1]), max(s_keys[2][1], s_keys[3][1]));
    const int mp = 1023 - (int)(kN & 1023u);
    const int mn = 1023 - (int)(kF & 1023u);

    // triplet terms (swap=True), eps added per element; 1 dim per thread
    const float pv = __ldg(&cent[mp * ND + d]);   // coalesced LDG.32
    const float nv = __ldg(&cent[mn * ND + d]);
    const float a = xv - pv + EPSV;
    const float b = xv - nv + EPSV;
    const float c = pv - nv + EPSV;
    // 2^16 fixed-point warp sums: one redux each, associative (deterministic)
    u32 q0 = __reduce_add_sync(0xffffffffu, __float2uint_rn(a * a * FPS));
    u32 q1 = __reduce_add_sync(0xffffffffu, __float2uint_rn(b * b * FPS));
    u32 q2 = __reduce_add_sync(0xffffffffu, __float2uint_rn(c * c * FPS));
    if (lane == 0) { s_part[warp][0] = q0; s_part[warp][1] = q1; s_part[warp][2] = q2; }
    __syncthreads();

    if (d == 0) {
        float r0 = (float)(s_part[0][0] + s_part[1][0] + s_part[2][0] + s_part[3][0]) * (1.0f / FPS);
        float r1 = (float)(s_part[0][1] + s_part[1][1] + s_part[2][1] + s_part[3][1]) * (1.0f / FPS);
        float r2 = (float)(s_part[0][2] + s_part[1][2] + s_part[2][2] + s_part[3][2]) * (1.0f / FPS);
        float dp = sqrtf(r0);
        float dn = fminf(sqrtf(r1), sqrtf(r2));
        float loss = fmaxf(dp - dn + 1.0f, 0.0f);

        // deterministic fixed-point accumulation with embedded row counter:
        // when the returned counter == NB-1, all other rows' sums are in.
        u64 fx = (u64)__double2ll_rn((double)loss * SCALE);
        u64 ret = atomicAdd(&g_accum, fx + (1ULL << CNT_SHIFT));
        if ((ret >> CNT_SHIFT) == (u64)(NB - 1)) {
            u64 total = (ret & ((1ULL << CNT_SHIFT) - 1)) + fx;
            out[0] = (float)((double)total * (1.0 / (4096.0 * SCALE)));
        }
    }
}

extern "C" void kernel_launch(void* const* d_in, const int* in_sizes, int n_in,
                              void* d_out, int out_size) {
    const float* input_features = (const float*)d_in[0];  // [4096, 128]
    const float* centroids      = (const float*)d_in[1];  // [1024, 128]
    float* out = (float*)d_out;

    sort_columns_kernel<<<ND, 1024>>>(centroids);
    row_kernel<<<NB, ND>>>(input_features, centroids, out);
}